// round 9
// baseline (speedup 1.0000x reference)
#include <cuda_runtime.h>
#include <cuda_fp16.h>
#include <cstdint>

#define TPB  512
#define TILE 128
#define WSTR 136   // weight smem row stride (elems), 128 cols padded
#define PSTR 72    // pos row stride (64 cols padded)
#define VSTR 40    // view row stride (32 cols padded)

// Single-fp16 weight scratch, row-major [1184][136], filled by prep kernel.
// Stage rows:  0 d1_W0(0,64)  1 d1_W1(64,128)  2 d1_W2(192,128)
//  3 d2_W0a(320,64)  4 d2_W0b(384,128)  5 d2_W1(512,128)  6 d2_W2(640,128)
//  7 d2_W3f(768,128) 8 c_W0a(896,32)   9 c_W0b(928,128) 10 c_W1p(1056,128)
__device__ __half g_w[1184 * WSTR];
__device__ float g_wd[128];

__constant__ int c_offs[11] = {0, 64, 192, 320, 384, 512, 640, 768, 896, 928, 1056};
__constant__ int c_rows[11] = {64, 128, 128, 64, 128, 128, 128, 128, 32, 128, 128};

__global__ void prep_kernel(const float* __restrict__ d1_W0, const float* __restrict__ d1_W1,
                            const float* __restrict__ d1_W2, const float* __restrict__ d2_W0,
                            const float* __restrict__ d2_W1, const float* __restrict__ d2_W2,
                            const float* __restrict__ d2_W3, const float* __restrict__ c_W0,
                            const float* __restrict__ c_W1) {
    int prow = blockIdx.x;      // 0..1183
    int n = threadIdx.x;        // 0..135
    int li = 0;
#pragma unroll
    for (int i = 1; i < 11; i++)
        if (prow >= c_offs[i]) li = i;
    int k = prow - c_offs[li];
    float v = 0.f;
    if (n < 128) {
        switch (li) {
            case 0: if (k < 63) v = d1_W0[k * 128 + n]; break;
            case 1: v = d1_W1[k * 128 + n]; break;
            case 2: v = d1_W2[k * 128 + n]; break;
            case 3: if (k < 63) v = d2_W0[k * 128 + n]; break;
            case 4: v = d2_W0[(63 + k) * 128 + n]; break;
            case 5: v = d2_W1[k * 128 + n]; break;
            case 6: v = d2_W2[k * 128 + n]; break;
            case 7: v = d2_W3[k * 129 + 1 + n]; break;          // feature cols
            case 8: if (k < 27) v = c_W0[k * 128 + n]; break;
            case 9: v = c_W0[(27 + k) * 128 + n]; break;
            case 10: if (n < 3) v = c_W1[k * 3 + n]; break;
        }
    }
    g_w[prow * WSTR + n] = __float2half_rn(v);
    if (prow == 0 && n < 128) g_wd[n] = d2_W3[n * 129];         // density col
}

__device__ __forceinline__ uint32_t sptr(const void* p) {
    return (uint32_t)__cvta_generic_to_shared(p);
}
__device__ __forceinline__ void ldm4(uint32_t& r0, uint32_t& r1, uint32_t& r2, uint32_t& r3, uint32_t a) {
    asm volatile("ldmatrix.sync.aligned.m8n8.x4.shared.b16 {%0,%1,%2,%3}, [%4];"
                 : "=r"(r0), "=r"(r1), "=r"(r2), "=r"(r3) : "r"(a));
}
__device__ __forceinline__ void ldm4t(uint32_t& r0, uint32_t& r1, uint32_t& r2, uint32_t& r3, uint32_t a) {
    asm volatile("ldmatrix.sync.aligned.m8n8.x4.trans.shared.b16 {%0,%1,%2,%3}, [%4];"
                 : "=r"(r0), "=r"(r1), "=r"(r2), "=r"(r3) : "r"(a));
}
__device__ __forceinline__ void ldm2t(uint32_t& r0, uint32_t& r1, uint32_t a) {
    asm volatile("ldmatrix.sync.aligned.m8n8.x2.trans.shared.b16 {%0,%1}, [%2];"
                 : "=r"(r0), "=r"(r1) : "r"(a));
}
__device__ __forceinline__ void mma_f16(float* c, const uint32_t* a, uint32_t b0, uint32_t b1) {
    asm volatile("mma.sync.aligned.m16n8k16.row.col.f32.f16.f16.f32 "
                 "{%0,%1,%2,%3}, {%4,%5,%6,%7}, {%8,%9}, {%0,%1,%2,%3};"
                 : "+f"(c[0]), "+f"(c[1]), "+f"(c[2]), "+f"(c[3])
                 : "r"(a[0]), "r"(a[1]), "r"(a[2]), "r"(a[3]), "r"(b0), "r"(b1));
}
__device__ __forceinline__ void cpa16cg(uint32_t s, const void* g) {
    asm volatile("cp.async.cg.shared.global [%0], [%1], 16;" :: "r"(s), "l"(g));
}
__device__ __forceinline__ void pair_bar(int pair) {
    asm volatile("bar.sync %0, 64;" :: "r"(pair + 1) : "memory");
}

// -------- SMEM map (bytes) --------
#define SM_W0    0                       // 34816 (128 x 136 x fp16)
#define SM_W1    34816
#define SM_POSH  69632                   // 128 x 72 x fp16 = 18432
#define SM_VIEWH 88064                   // 128 x 40 x fp16 = 10240
#define SM_EXCH  98304                   // 8 pairs x 2 halves x 2048 = 32768
#define SM_WD    131072                  // 128 f32
#define SM_DENS  131584                  // 2 x 128 f32
#define SM_OSTG  132608                  // 128 x 4 f32
#define SMEM_TOTAL 134656

__global__ void __launch_bounds__(TPB, 1)
nerf_main(const float* __restrict__ x, float* __restrict__ out) {
    extern __shared__ __align__(16) char smem[];
    const uint32_t sb = sptr(smem);
    __half* posH  = (__half*)(smem + SM_POSH);
    __half* viewH = (__half*)(smem + SM_VIEWH);
    float* swd  = (float*)(smem + SM_WD);
    float* dens = (float*)(smem + SM_DENS);
    float* ostg = (float*)(smem + SM_OSTG);

    const int tid  = threadIdx.x;
    const int lane = tid & 31;
    const int warp = tid >> 5;
    const int pair = warp & 7;           // row-tile index (16 rows each)
    const int half = warp >> 3;          // output-column half (0: cols 0-63, 1: 64-127)
    const int r0   = pair * 16;
    const int npb  = half * 4;           // np base (16-col units) for addresses only
    const size_t tile = blockIdx.x;

    auto loadW = [&](int st) {                          // into buffer st&1
        const uint32_t b = sb + ((st & 1) ? SM_W1 : SM_W0);
        const __half* g = g_w + c_offs[st] * WSTR;
        const int chunks = c_rows[st] * 17;             // 16B chunks
        for (int i = tid; i < chunks; i += TPB)
            cpa16cg(b + i * 16, g + i * 8);
        asm volatile("cp.async.commit_group;" ::: "memory");
    };

    // stage-0 weights in flight during input staging
    loadW(0);

    // zero pos/view buffers (padded cols must be 0), load density weights
    {
        uint4* pz = (uint4*)(smem + SM_POSH);
        for (int i = tid; i < (SM_EXCH - SM_POSH) / 16; i += TPB)
            pz[i] = make_uint4(0, 0, 0, 0);
        if (tid < 128) swd[tid] = g_wd[tid];
    }
    __syncthreads();
    {
        const float* xt = x + tile * (size_t)(TILE * 90);
        for (int i = tid; i < TILE * 90; i += TPB) {
            int row = i / 90, c = i - row * 90;
            __half h = __float2half_rn(xt[i]);
            if (c < 63) posH[row * PSTR + c] = h;
            else        viewH[row * VSTR + c - 63] = h;
        }
    }

    float acc[8][4];                     // 8 n8-tiles: cols half*64 + 8t
    uint32_t aH[8][4];                   // full K=128 A fragments (post-exchange)
    const int krow = lane & 15;
    const int nsel = (lane >> 4) * 8;
    const int rq = lane >> 2, m = lane & 3;
    const int row0 = r0 + rq;

    auto zero_acc = [&]() {
#pragma unroll
        for (int t = 0; t < 8; t++)
#pragma unroll
            for (int j = 0; j < 4; j++) acc[t][j] = 0.f;
    };
    auto relu_acc = [&]() {
#pragma unroll
        for (int t = 0; t < 8; t++)
#pragma unroll
            for (int j = 0; j < 4; j++) acc[t][j] = fmaxf(acc[t][j], 0.f);
    };
    // own acc -> fp16 frags (own K-quarter), exchange with partner warp.
    // ALL aH indices are compile-time constants (branch on half) — no spills.
    auto split_exch = [&](bool dorelu) {
        uint32_t* myB = (uint32_t*)(smem + SM_EXCH + pair * 4096 + half * 2048) + lane;
#pragma unroll
        for (int kl = 0; kl < 4; kl++) {
            uint32_t f4[4];
#pragma unroll
            for (int h = 0; h < 2; h++)
#pragma unroll
                for (int p = 0; p < 2; p++) {
                    float v0 = acc[2 * kl + h][2 * p];
                    float v1 = acc[2 * kl + h][2 * p + 1];
                    if (dorelu) { v0 = fmaxf(v0, 0.f); v1 = fmaxf(v1, 0.f); }
                    __half2 hh = __floats2half2_rn(v0, v1);
                    f4[h * 2 + p] = reinterpret_cast<uint32_t&>(hh);
                }
#pragma unroll
            for (int f = 0; f < 4; f++) myB[(kl * 4 + f) * 32] = f4[f];
            if (half == 0) {
#pragma unroll
                for (int f = 0; f < 4; f++) aH[kl][f] = f4[f];
            } else {
#pragma unroll
                for (int f = 0; f < 4; f++) aH[4 + kl][f] = f4[f];
            }
        }
        pair_bar(pair);
        const uint32_t* pB = (const uint32_t*)(smem + SM_EXCH + pair * 4096 + (1 - half) * 2048) + lane;
        if (half == 0) {
#pragma unroll
            for (int kl = 0; kl < 4; kl++)
#pragma unroll
                for (int f = 0; f < 4; f++) aH[4 + kl][f] = pB[(kl * 4 + f) * 32];
        } else {
#pragma unroll
            for (int kl = 0; kl < 4; kl++)
#pragma unroll
                for (int f = 0; f < 4; f++) aH[kl][f] = pB[(kl * 4 + f) * 32];
        }
    };
    // A from smem (pos/view), this warp's np half
    auto mma_smem = [&](const __half* AH, int astr, int KT, uint32_t wb) {
        uint32_t bH = sptr(AH);
        int arow = r0 + (lane & 15);
        int acol = (lane >> 4) * 8;
        for (int kt = 0; kt < KT; kt++) {
            uint32_t ta[4];
            uint32_t ao = (uint32_t)(arow * astr + kt * 16 + acol) * 2;
            ldm4(ta[0], ta[1], ta[2], ta[3], bH + ao);
#pragma unroll
            for (int npl = 0; npl < 4; npl++) {
                uint32_t b0, b1, b2, b3;
                uint32_t wo = (uint32_t)((kt * 16 + krow) * WSTR + (npb + npl) * 16 + nsel) * 2;
                ldm4t(b0, b1, b2, b3, wb + wo);
                mma_f16(acc[2 * npl], ta, b0, b1);
                mma_f16(acc[2 * npl + 1], ta, b2, b3);
            }
        }
    };
    // A from register fragments, K=128, this warp's np half
    auto mma_reg = [&](uint32_t wb) {
#pragma unroll
        for (int kt = 0; kt < 8; kt++)
#pragma unroll
            for (int npl = 0; npl < 4; npl++) {
                uint32_t b0, b1, b2, b3;
                uint32_t wo = (uint32_t)((kt * 16 + krow) * WSTR + (npb + npl) * 16 + nsel) * 2;
                ldm4t(b0, b1, b2, b3, wb + wo);
                mma_f16(acc[2 * npl], aH[kt], b0, b1);
                mma_f16(acc[2 * npl + 1], aH[kt], b2, b3);
            }
    };

    zero_acc();
    for (int st = 0; st < 11; st++) {
        __syncthreads();                                // buffer (st+1)&1 free
        if (st < 10) loadW(st + 1);                     // prefetch next stage

        // ---- stage-boundary register work ----
        if (st == 7) {                                  // density from relu'd h5
            relu_acc();
            float d0 = 0.f, d1 = 0.f;
#pragma unroll
            for (int t = 0; t < 8; t++) {
                int col0 = half * 64 + 8 * t + 2 * m;
                float w0 = swd[col0], w1 = swd[col0 + 1];
                d0 += acc[t][0] * w0 + acc[t][1] * w1;
                d1 += acc[t][2] * w0 + acc[t][3] * w1;
            }
            d0 += __shfl_xor_sync(~0u, d0, 1); d0 += __shfl_xor_sync(~0u, d0, 2);
            d1 += __shfl_xor_sync(~0u, d1, 1); d1 += __shfl_xor_sync(~0u, d1, 2);
            if (m == 0) { dens[half * 128 + row0] = d0; dens[half * 128 + row0 + 8] = d1; }
            split_exch(false);                          // acc already relu'd; pair_bar inside
            if (half == 0 && m == 0) {
                ostg[row0 * 4 + 3]       = d0 + dens[128 + row0];
                ostg[(row0 + 8) * 4 + 3] = d1 + dens[128 + row0 + 8];
            }
            zero_acc();
        } else if (st >= 1 && st != 4 && st != 9) {
            split_exch(st <= 6 || st == 10);            // relu except feature path
            if (st != 10) zero_acc();
        }

        // weights for stage st were issued at stage st-1 (or pre-staging)
        if (st < 10) asm volatile("cp.async.wait_group 1;" ::: "memory");
        else         asm volatile("cp.async.wait_group 0;" ::: "memory");
        __syncthreads();

        const uint32_t wb = sb + ((st & 1) ? SM_W1 : SM_W0);
        if (st == 0 || st == 3)      mma_smem(posH, PSTR, 4, wb);
        else if (st == 8)            mma_smem(viewH, VSTR, 2, wb);
        else if (st == 10) {                            // rgb: cols 0..7, half 0 only
            if (half == 0) {
                float c8[4] = {0.f, 0.f, 0.f, 0.f};
#pragma unroll
                for (int kt = 0; kt < 8; kt++) {
                    uint32_t b0, b1;
                    uint32_t wo = (uint32_t)((kt * 16 + krow) * WSTR) * 2;
                    ldm2t(b0, b1, wb + wo);
                    mma_f16(c8, aH[kt], b0, b1);
                }
                if (2 * m < 3)     { ostg[row0 * 4 + 2 * m] = c8[0];     ostg[(row0 + 8) * 4 + 2 * m] = c8[2]; }
                if (2 * m + 1 < 3) { ostg[row0 * 4 + 2 * m + 1] = c8[1]; ostg[(row0 + 8) * 4 + 2 * m + 1] = c8[3]; }
            }
        } else                        mma_reg(wb);
    }

    __syncthreads();
    if (tid < TILE)
        ((float4*)out)[tile * TILE + tid] = ((const float4*)ostg)[tid];
}

extern "C" void kernel_launch(void* const* d_in, const int* in_sizes, int n_in,
                              void* d_out, int out_size) {
    const float* x     = (const float*)d_in[0];
    const float* d1_W0 = (const float*)d_in[1];
    const float* d1_W1 = (const float*)d_in[2];
    const float* d1_W2 = (const float*)d_in[3];
    const float* d2_W0 = (const float*)d_in[4];
    const float* d2_W1 = (const float*)d_in[5];
    const float* d2_W2 = (const float*)d_in[6];
    const float* d2_W3 = (const float*)d_in[7];
    const float* c_W0  = (const float*)d_in[8];
    const float* c_W1  = (const float*)d_in[9];
    const int N = in_sizes[0] / 90;

    prep_kernel<<<1184, WSTR>>>(d1_W0, d1_W1, d1_W2, d2_W0, d2_W1, d2_W2, d2_W3, c_W0, c_W1);
    cudaFuncSetAttribute(nerf_main, cudaFuncAttributeMaxDynamicSharedMemorySize, SMEM_TOTAL);
    nerf_main<<<N / TILE, TPB, SMEM_TOTAL>>>(x, (float*)d_out);
}

// round 10
// speedup vs baseline: 2.0711x; 2.0711x over previous
#include <cuda_runtime.h>
#include <cuda_fp16.h>
#include <cstdint>

#define TPB  256
#define TILE 128
#define WSTR 136   // weight smem row stride (elems), 128 cols padded
#define ASTR 136   // activation smem row stride (elems)
#define PSTR 72    // pos row stride (64 cols padded)
#define VSTR 40    // view row stride (32 cols padded)

// Single-fp16 weight scratch, row-major [1184][136], filled by prep kernel.
// Stage rows:  0 d1_W0(0,64)  1 d1_W1(64,128)  2 d1_W2(192,128)
//  3 d2_W0a(320,64)  4 d2_W0b(384,128)  5 d2_W1(512,128)  6 d2_W2(640,128)
//  7 d2_W3f(768,128) 8 c_W0a(896,32)   9 c_W0b(928,128) 10 c_W1p(1056,128)
__device__ __half g_w[1184 * WSTR];
__device__ float g_wd[128];

__constant__ int c_offs[11] = {0, 64, 192, 320, 384, 512, 640, 768, 896, 928, 1056};
__constant__ int c_rows[11] = {64, 128, 128, 64, 128, 128, 128, 128, 32, 128, 128};

__global__ void prep_kernel(const float* __restrict__ d1_W0, const float* __restrict__ d1_W1,
                            const float* __restrict__ d1_W2, const float* __restrict__ d2_W0,
                            const float* __restrict__ d2_W1, const float* __restrict__ d2_W2,
                            const float* __restrict__ d2_W3, const float* __restrict__ c_W0,
                            const float* __restrict__ c_W1) {
    int prow = blockIdx.x;      // 0..1183
    int n = threadIdx.x;        // 0..135
    int li = 0;
#pragma unroll
    for (int i = 1; i < 11; i++)
        if (prow >= c_offs[i]) li = i;
    int k = prow - c_offs[li];
    float v = 0.f;
    if (n < 128) {
        switch (li) {
            case 0: if (k < 63) v = d1_W0[k * 128 + n]; break;
            case 1: v = d1_W1[k * 128 + n]; break;
            case 2: v = d1_W2[k * 128 + n]; break;
            case 3: if (k < 63) v = d2_W0[k * 128 + n]; break;
            case 4: v = d2_W0[(63 + k) * 128 + n]; break;
            case 5: v = d2_W1[k * 128 + n]; break;
            case 6: v = d2_W2[k * 128 + n]; break;
            case 7: v = d2_W3[k * 129 + 1 + n]; break;          // feature cols
            case 8: if (k < 27) v = c_W0[k * 128 + n]; break;
            case 9: v = c_W0[(27 + k) * 128 + n]; break;
            case 10: if (n < 3) v = c_W1[k * 3 + n]; break;
        }
    }
    g_w[prow * WSTR + n] = __float2half_rn(v);
    if (prow == 0 && n < 128) g_wd[n] = d2_W3[n * 129];         // density col
}

__device__ __forceinline__ uint32_t sptr(const void* p) {
    return (uint32_t)__cvta_generic_to_shared(p);
}
__device__ __forceinline__ void ldm4(uint32_t& r0, uint32_t& r1, uint32_t& r2, uint32_t& r3, uint32_t a) {
    asm volatile("ldmatrix.sync.aligned.m8n8.x4.shared.b16 {%0,%1,%2,%3}, [%4];"
                 : "=r"(r0), "=r"(r1), "=r"(r2), "=r"(r3) : "r"(a));
}
__device__ __forceinline__ void ldm4t(uint32_t& r0, uint32_t& r1, uint32_t& r2, uint32_t& r3, uint32_t a) {
    asm volatile("ldmatrix.sync.aligned.m8n8.x4.trans.shared.b16 {%0,%1,%2,%3}, [%4];"
                 : "=r"(r0), "=r"(r1), "=r"(r2), "=r"(r3) : "r"(a));
}
__device__ __forceinline__ void ldm2t(uint32_t& r0, uint32_t& r1, uint32_t a) {
    asm volatile("ldmatrix.sync.aligned.m8n8.x2.trans.shared.b16 {%0,%1}, [%2];"
                 : "=r"(r0), "=r"(r1) : "r"(a));
}
__device__ __forceinline__ void mma_f16(float* c, const uint32_t* a, uint32_t b0, uint32_t b1) {
    asm volatile("mma.sync.aligned.m16n8k16.row.col.f32.f16.f16.f32 "
                 "{%0,%1,%2,%3}, {%4,%5,%6,%7}, {%8,%9}, {%0,%1,%2,%3};"
                 : "+f"(c[0]), "+f"(c[1]), "+f"(c[2]), "+f"(c[3])
                 : "r"(a[0]), "r"(a[1]), "r"(a[2]), "r"(a[3]), "r"(b0), "r"(b1));
}
__device__ __forceinline__ void cpa16cg(uint32_t s, const void* g) {
    asm volatile("cp.async.cg.shared.global [%0], [%1], 16;" :: "r"(s), "l"(g));
}

// -------- SMEM map (bytes): single weight buffer + SMEM activations --------
#define SM_W     0                       // 34816 (128 x 136 x fp16)
#define SM_ACT   34816                   // 34816 (128 x 136 x fp16)
#define SM_POS   69632                   // 128 x 72 x fp16 = 18432
#define SM_VIEW  88064                   // 128 x 40 x fp16 = 10240
#define SM_WD    98304                   // 128 f32
#define SM_OSTG  98816                   // 128 x 4 f32
#define SMEM_TOTAL 100864

__global__ void __launch_bounds__(TPB, 2)
nerf_main(const float* __restrict__ x, float* __restrict__ out) {
    extern __shared__ __align__(16) char smem[];
    const uint32_t sb = sptr(smem);
    __half* posH  = (__half*)(smem + SM_POS);
    __half* viewH = (__half*)(smem + SM_VIEW);
    float* swd  = (float*)(smem + SM_WD);
    float* ostg = (float*)(smem + SM_OSTG);

    const int tid  = threadIdx.x;
    const int lane = tid & 31;
    const int warp = tid >> 5;
    const int r0   = warp * 16;
    const size_t tile = blockIdx.x;

    auto loadW = [&](int st) {
        const __half* g = g_w + c_offs[st] * WSTR;
        const int chunks = c_rows[st] * 17;             // 16B chunks
        for (int i = tid; i < chunks; i += TPB)
            cpa16cg(sb + SM_W + i * 16, g + i * 8);
        asm volatile("cp.async.commit_group;" ::: "memory");
    };

    // stage-0 weights in flight during input staging
    loadW(0);

    // zero pos/view buffers (padded cols must be 0), load density weights
    {
        uint4* pz = (uint4*)(smem + SM_POS);
        for (int i = tid; i < (SM_WD - SM_POS) / 16; i += TPB)
            pz[i] = make_uint4(0, 0, 0, 0);
        if (tid < 128) swd[tid] = g_wd[tid];
    }
    __syncthreads();
    {
        const float* xt = x + tile * (size_t)(TILE * 90);
        for (int i = tid; i < TILE * 90; i += TPB) {
            int row = i / 90, c = i - row * 90;
            __half h = __float2half_rn(xt[i]);
            if (c < 63) posH[row * PSTR + c] = h;
            else        viewH[row * VSTR + c - 63] = h;
        }
    }
    asm volatile("cp.async.wait_group 0;" ::: "memory");
    __syncthreads();

    float acc[16][4];
    const int krow = lane & 15;
    const int nsel = (lane >> 4) * 8;
    const int rq = lane >> 2, m = lane & 3;
    const int row0 = r0 + rq;
    const uint32_t wb = sb + SM_W;
    const uint32_t ab = sb + SM_ACT;

    auto zero_acc = [&]() {
#pragma unroll
        for (int t = 0; t < 16; t++)
#pragma unroll
            for (int j = 0; j < 4; j++) acc[t][j] = 0.f;
    };
    auto relu_acc = [&]() {
#pragma unroll
        for (int t = 0; t < 16; t++)
#pragma unroll
            for (int j = 0; j < 4; j++) acc[t][j] = fmaxf(acc[t][j], 0.f);
    };
    // accumulators -> fp16 activations in SMEM (row-major, conflict-free STS)
    auto act_store = [&](bool dorelu) {
#pragma unroll
        for (int t = 0; t < 16; t++) {
            float v0 = acc[t][0], v1 = acc[t][1], v2 = acc[t][2], v3 = acc[t][3];
            if (dorelu) {
                v0 = fmaxf(v0, 0.f); v1 = fmaxf(v1, 0.f);
                v2 = fmaxf(v2, 0.f); v3 = fmaxf(v3, 0.f);
            }
            __half2 h01 = __floats2half2_rn(v0, v1);
            __half2 h23 = __floats2half2_rn(v2, v3);
            uint32_t co = (uint32_t)(8 * t + 2 * m) * 2;
            asm volatile("st.shared.b32 [%0], %1;"
                         :: "r"(ab + (uint32_t)(row0 * ASTR) * 2 + co),
                            "r"(reinterpret_cast<uint32_t&>(h01)) : "memory");
            asm volatile("st.shared.b32 [%0], %1;"
                         :: "r"(ab + (uint32_t)((row0 + 8) * ASTR) * 2 + co),
                            "r"(reinterpret_cast<uint32_t&>(h23)) : "memory");
        }
    };
    // unified MMA: A (fp16) from SMEM via ldmatrix, B weights from SM_W
    auto mma_src = [&](uint32_t bA, int astr, int KT) {
        const int arow = r0 + krow;
        for (int kt = 0; kt < KT; kt++) {
            uint32_t ta[4];
            uint32_t ao = (uint32_t)(arow * astr + kt * 16 + nsel) * 2;
            ldm4(ta[0], ta[1], ta[2], ta[3], bA + ao);
#pragma unroll
            for (int np = 0; np < 8; np++) {
                uint32_t b0, b1, b2, b3;
                uint32_t wo = (uint32_t)((kt * 16 + krow) * WSTR + np * 16 + nsel) * 2;
                ldm4t(b0, b1, b2, b3, wb + wo);
                mma_f16(acc[2 * np], ta, b0, b1);
                mma_f16(acc[2 * np + 1], ta, b2, b3);
            }
        }
    };

    zero_acc();
    for (int st = 0; st < 11; st++) {
        __syncthreads();                    // all warps done with W + act of prev stage
        if (st >= 1) loadW(st);             // into the single buffer (st0 preloaded)

        // ---- stage-boundary register/SMEM work (overlaps in-flight cp.async) ----
        if (st == 7) {                      // density from relu'd h5
            relu_acc();
            float d0 = 0.f, d1 = 0.f;
#pragma unroll
            for (int t = 0; t < 16; t++) {
                float w0 = swd[8 * t + 2 * m], w1 = swd[8 * t + 2 * m + 1];
                d0 += acc[t][0] * w0 + acc[t][1] * w1;
                d1 += acc[t][2] * w0 + acc[t][3] * w1;
            }
            d0 += __shfl_xor_sync(~0u, d0, 1); d0 += __shfl_xor_sync(~0u, d0, 2);
            d1 += __shfl_xor_sync(~0u, d1, 1); d1 += __shfl_xor_sync(~0u, d1, 2);
            if (m == 0) { ostg[row0 * 4 + 3] = d0; ostg[(row0 + 8) * 4 + 3] = d1; }
        }
        if (st >= 1 && st != 4 && st != 9) {
            act_store(st <= 6 || st == 10); // relu except feature/out2 paths (st7 pre-relu'd)
            if (st != 10) zero_acc();
        }

        if (st >= 1) asm volatile("cp.async.wait_group 0;" ::: "memory");
        __syncthreads();                    // act visible + weights resident

        if (st == 0 || st == 3)      mma_src(sptr(posH), PSTR, 4);
        else if (st == 8)            mma_src(sptr(viewH), VSTR, 2);
        else if (st == 10) {                // rgb: K=128, N=8 (3 real)
            float c8[4] = {0.f, 0.f, 0.f, 0.f};
            const int arow = r0 + krow;
            for (int kt = 0; kt < 8; kt++) {
                uint32_t ta[4];
                uint32_t ao = (uint32_t)(arow * ASTR + kt * 16 + nsel) * 2;
                ldm4(ta[0], ta[1], ta[2], ta[3], ab + ao);
                uint32_t b0, b1;
                uint32_t wo = (uint32_t)((kt * 16 + krow) * WSTR) * 2;
                ldm2t(b0, b1, wb + wo);
                mma_f16(c8, ta, b0, b1);
            }
            if (2 * m < 3)     { ostg[row0 * 4 + 2 * m] = c8[0];     ostg[(row0 + 8) * 4 + 2 * m] = c8[2]; }
            if (2 * m + 1 < 3) { ostg[row0 * 4 + 2 * m + 1] = c8[1]; ostg[(row0 + 8) * 4 + 2 * m + 1] = c8[3]; }
        } else                        mma_src(ab, ASTR, 8);
    }

    __syncthreads();
    if (tid < TILE)
        ((float4*)out)[tile * TILE + tid] = ((const float4*)ostg)[tid];
}

extern "C" void kernel_launch(void* const* d_in, const int* in_sizes, int n_in,
                              void* d_out, int out_size) {
    const float* x     = (const float*)d_in[0];
    const float* d1_W0 = (const float*)d_in[1];
    const float* d1_W1 = (const float*)d_in[2];
    const float* d1_W2 = (const float*)d_in[3];
    const float* d2_W0 = (const float*)d_in[4];
    const float* d2_W1 = (const float*)d_in[5];
    const float* d2_W2 = (const float*)d_in[6];
    const float* d2_W3 = (const float*)d_in[7];
    const float* c_W0  = (const float*)d_in[8];
    const float* c_W1  = (const float*)d_in[9];
    const int N = in_sizes[0] / 90;

    prep_kernel<<<1184, WSTR>>>(d1_W0, d1_W1, d1_W2, d2_W0, d2_W1, d2_W2, d2_W3, c_W0, c_W1);
    cudaFuncSetAttribute(nerf_main, cudaFuncAttributeMaxDynamicSharedMemorySize, SMEM_TOTAL);
    nerf_main<<<N / TILE, TPB, SMEM_TOTAL>>>(x, (float*)d_out);
}

// round 12
// speedup vs baseline: 2.2233x; 1.0735x over previous
#include <cuda_runtime.h>
#include <cuda_fp16.h>
#include <cstdint>

#define TPB  256
#define TILE 128
#define WSTR 136   // weight smem row stride (elems), 128 cols padded
#define ASTR 136   // activation smem row stride (elems)
#define PSTR 72    // pos row stride (64 cols padded)
#define VSTR 40    // view row stride (32 cols padded)

// Single-fp16 weight scratch, row-major [1184][136], filled by prep kernel.
// Stage rows:  0 d1_W0(0,64)  1 d1_W1(64,128)  2 d1_W2(192,128)
//  3 d2_W0a(320,64)  4 d2_W0b(384,128)  5 d2_W1(512,128)  6 d2_W2(640,128)
//  7 d2_W3f(768,128) 8 c_W0a(896,32)   9 c_W0b(928,128) 10 c_W1p(1056,128)
__device__ __half g_w[1184 * WSTR];
__device__ float g_wd[128];

__constant__ int c_offs[11] = {0, 64, 192, 320, 384, 512, 640, 768, 896, 928, 1056};
__constant__ int c_rows[11] = {64, 128, 128, 64, 128, 128, 128, 128, 32, 128, 128};

__global__ void prep_kernel(const float* __restrict__ d1_W0, const float* __restrict__ d1_W1,
                            const float* __restrict__ d1_W2, const float* __restrict__ d2_W0,
                            const float* __restrict__ d2_W1, const float* __restrict__ d2_W2,
                            const float* __restrict__ d2_W3, const float* __restrict__ c_W0,
                            const float* __restrict__ c_W1) {
    int prow = blockIdx.x;      // 0..1183
    int n = threadIdx.x;        // 0..135
    int li = 0;
#pragma unroll
    for (int i = 1; i < 11; i++)
        if (prow >= c_offs[i]) li = i;
    int k = prow - c_offs[li];
    float v = 0.f;
    if (n < 128) {
        switch (li) {
            case 0: if (k < 63) v = d1_W0[k * 128 + n]; break;
            case 1: v = d1_W1[k * 128 + n]; break;
            case 2: v = d1_W2[k * 128 + n]; break;
            case 3: if (k < 63) v = d2_W0[k * 128 + n]; break;
            case 4: v = d2_W0[(63 + k) * 128 + n]; break;
            case 5: v = d2_W1[k * 128 + n]; break;
            case 6: v = d2_W2[k * 128 + n]; break;
            case 7: v = d2_W3[k * 129 + 1 + n]; break;          // feature cols
            case 8: if (k < 27) v = c_W0[k * 128 + n]; break;
            case 9: v = c_W0[(27 + k) * 128 + n]; break;
            case 10: if (n < 3) v = c_W1[k * 3 + n]; break;
        }
    }
    g_w[prow * WSTR + n] = __float2half_rn(v);
    if (prow == 0 && n < 128) g_wd[n] = d2_W3[n * 129];         // density col
}

__device__ __forceinline__ uint32_t sptr(const void* p) {
    return (uint32_t)__cvta_generic_to_shared(p);
}
__device__ __forceinline__ void ldm4(uint32_t& r0, uint32_t& r1, uint32_t& r2, uint32_t& r3, uint32_t a) {
    asm volatile("ldmatrix.sync.aligned.m8n8.x4.shared.b16 {%0,%1,%2,%3}, [%4];"
                 : "=r"(r0), "=r"(r1), "=r"(r2), "=r"(r3) : "r"(a));
}
__device__ __forceinline__ void ldm4t(uint32_t& r0, uint32_t& r1, uint32_t& r2, uint32_t& r3, uint32_t a) {
    asm volatile("ldmatrix.sync.aligned.m8n8.x4.trans.shared.b16 {%0,%1,%2,%3}, [%4];"
                 : "=r"(r0), "=r"(r1), "=r"(r2), "=r"(r3) : "r"(a));
}
__device__ __forceinline__ void ldm2t(uint32_t& r0, uint32_t& r1, uint32_t a) {
    asm volatile("ldmatrix.sync.aligned.m8n8.x2.trans.shared.b16 {%0,%1}, [%2];"
                 : "=r"(r0), "=r"(r1) : "r"(a));
}
__device__ __forceinline__ void mma_f16(float* c, const uint32_t* a, uint32_t b0, uint32_t b1) {
    asm volatile("mma.sync.aligned.m16n8k16.row.col.f32.f16.f16.f32 "
                 "{%0,%1,%2,%3}, {%4,%5,%6,%7}, {%8,%9}, {%0,%1,%2,%3};"
                 : "+f"(c[0]), "+f"(c[1]), "+f"(c[2]), "+f"(c[3])
                 : "r"(a[0]), "r"(a[1]), "r"(a[2]), "r"(a[3]), "r"(b0), "r"(b1));
}
__device__ __forceinline__ void cpa16cg(uint32_t s, const void* g) {
    asm volatile("cp.async.cg.shared.global [%0], [%1], 16;" :: "r"(s), "l"(g));
}

// -------- SMEM map (bytes): single weight buffer + SMEM activations --------
#define SM_W     0                       // 34816 (128 x 136 x fp16)
#define SM_ACT   34816                   // 34816 (128 x 136 x fp16)
#define SM_POS   69632                   // 128 x 72 x fp16 = 18432
#define SM_VIEW  88064                   // 128 x 40 x fp16 = 10240
#define SM_WD    98304                   // 128 f32
#define SM_DENS  98816                   // 2 x 128 f32 = 1024
#define SM_OSTG  99840                   // 128 x 4 f32
#define SMEM_TOTAL 101888

__global__ void __launch_bounds__(TPB, 2)
nerf_main(const float* __restrict__ x, float* __restrict__ out) {
    extern __shared__ __align__(16) char smem[];
    const uint32_t sb = sptr(smem);
    __half* posH  = (__half*)(smem + SM_POS);
    __half* viewH = (__half*)(smem + SM_VIEW);
    float* swd  = (float*)(smem + SM_WD);
    float* dens = (float*)(smem + SM_DENS);
    float* ostg = (float*)(smem + SM_OSTG);

    const int tid  = threadIdx.x;
    const int lane = tid & 31;
    const int warp = tid >> 5;
    const int group = warp >> 1;         // 0..3: rows group*32 .. +31
    const int half  = warp & 1;          // output-column half (0: cols 0-63, 1: 64-127)
    const int r0    = group * 32;
    const int npb   = half * 4;          // np base (16-col units)
    const size_t tile = blockIdx.x;

    auto loadW = [&](int st) {
        const __half* g = g_w + c_offs[st] * WSTR;
        const int chunks = c_rows[st] * 17;             // 16B chunks
        for (int i = tid; i < chunks; i += TPB)
            cpa16cg(sb + SM_W + i * 16, g + i * 8);
        asm volatile("cp.async.commit_group;" ::: "memory");
    };

    // stage-0 weights in flight during input staging
    loadW(0);

    // zero pos/view buffers (padded cols must be 0), load density weights
    {
        uint4* pz = (uint4*)(smem + SM_POS);
        for (int i = tid; i < (SM_WD - SM_POS) / 16; i += TPB)
            pz[i] = make_uint4(0, 0, 0, 0);
        if (tid < 128) swd[tid] = g_wd[tid];
    }
    __syncthreads();
    {
        const float* xt = x + tile * (size_t)(TILE * 90);
        for (int i = tid; i < TILE * 90; i += TPB) {
            int row = i / 90, c = i - row * 90;
            __half h = __float2half_rn(xt[i]);
            if (c < 63) posH[row * PSTR + c] = h;
            else        viewH[row * VSTR + c - 63] = h;
        }
    }
    asm volatile("cp.async.wait_group 0;" ::: "memory");
    __syncthreads();

    // acc tile t = mt*8 + npl*2 + h : rows r0+mt*16, cols half*64 + npl*16 + 8h
    float acc[16][4];
    const int krow = lane & 15;
    const int nsel = (lane >> 4) * 8;
    const int rq = lane >> 2, m = lane & 3;
    const int row0 = r0 + rq;
    const uint32_t wb = sb + SM_W;
    const uint32_t ab = sb + SM_ACT;

    auto zero_acc = [&]() {
#pragma unroll
        for (int t = 0; t < 16; t++)
#pragma unroll
            for (int j = 0; j < 4; j++) acc[t][j] = 0.f;
    };
    auto relu_acc = [&]() {
#pragma unroll
        for (int t = 0; t < 16; t++)
#pragma unroll
            for (int j = 0; j < 4; j++) acc[t][j] = fmaxf(acc[t][j], 0.f);
    };
    // accumulators -> fp16 activations in SMEM (warp's 32x64 quadrant)
    auto act_store = [&](bool dorelu) {
#pragma unroll
        for (int mt = 0; mt < 2; mt++)
#pragma unroll
            for (int npl = 0; npl < 4; npl++)
#pragma unroll
                for (int h = 0; h < 2; h++) {
                    const int t = mt * 8 + npl * 2 + h;
                    float v0 = acc[t][0], v1 = acc[t][1], v2 = acc[t][2], v3 = acc[t][3];
                    if (dorelu) {
                        v0 = fmaxf(v0, 0.f); v1 = fmaxf(v1, 0.f);
                        v2 = fmaxf(v2, 0.f); v3 = fmaxf(v3, 0.f);
                    }
                    __half2 h01 = __floats2half2_rn(v0, v1);
                    __half2 h23 = __floats2half2_rn(v2, v3);
                    const uint32_t co = (uint32_t)(half * 64 + npl * 16 + 8 * h + 2 * m) * 2;
                    const int rA = row0 + mt * 16;
                    asm volatile("st.shared.b32 [%0], %1;"
                                 :: "r"(ab + (uint32_t)(rA * ASTR) * 2 + co),
                                    "r"(reinterpret_cast<uint32_t&>(h01)) : "memory");
                    asm volatile("st.shared.b32 [%0], %1;"
                                 :: "r"(ab + (uint32_t)((rA + 8) * ASTR) * 2 + co),
                                    "r"(reinterpret_cast<uint32_t&>(h23)) : "memory");
                }
    };
    // unified MMA: M=32 (2 m16 frags), N=64 (this warp's half), A via ldmatrix
    auto mma_src = [&](uint32_t bA, int astr, int KT) {
        const int arow = r0 + krow;
        for (int kt = 0; kt < KT; kt++) {
            uint32_t ta0[4], ta1[4];
            uint32_t ao = (uint32_t)(arow * astr + kt * 16 + nsel) * 2;
            ldm4(ta0[0], ta0[1], ta0[2], ta0[3], bA + ao);
            ldm4(ta1[0], ta1[1], ta1[2], ta1[3], bA + ao + (uint32_t)(16 * astr) * 2);
#pragma unroll
            for (int npl = 0; npl < 4; npl++) {
                uint32_t b0, b1, b2, b3;
                uint32_t wo = (uint32_t)((kt * 16 + krow) * WSTR + (npb + npl) * 16 + nsel) * 2;
                ldm4t(b0, b1, b2, b3, wb + wo);
                mma_f16(acc[npl * 2],     ta0, b0, b1);
                mma_f16(acc[npl * 2 + 1], ta0, b2, b3);
                mma_f16(acc[8 + npl * 2],     ta1, b0, b1);
                mma_f16(acc[8 + npl * 2 + 1], ta1, b2, b3);
            }
        }
    };

    zero_acc();
    for (int st = 0; st < 11; st++) {
        __syncthreads();                    // all warps done with W + act of prev stage
        if (st >= 1) loadW(st);             // into the single buffer (st0 preloaded)

        // ---- stage-boundary register/SMEM work (overlaps in-flight cp.async) ----
        if (st == 7) {                      // density partials from relu'd h5 (this half)
            relu_acc();
            float d00 = 0.f, d01 = 0.f, d10 = 0.f, d11 = 0.f;
#pragma unroll
            for (int npl = 0; npl < 4; npl++)
#pragma unroll
                for (int h = 0; h < 2; h++) {
                    const int col = half * 64 + npl * 16 + 8 * h + 2 * m;
                    const float w0 = swd[col], w1 = swd[col + 1];
                    const int t0 = npl * 2 + h, t1 = 8 + npl * 2 + h;
                    d00 += acc[t0][0] * w0 + acc[t0][1] * w1;
                    d01 += acc[t0][2] * w0 + acc[t0][3] * w1;
                    d10 += acc[t1][0] * w0 + acc[t1][1] * w1;
                    d11 += acc[t1][2] * w0 + acc[t1][3] * w1;
                }
            d00 += __shfl_xor_sync(~0u, d00, 1); d00 += __shfl_xor_sync(~0u, d00, 2);
            d01 += __shfl_xor_sync(~0u, d01, 1); d01 += __shfl_xor_sync(~0u, d01, 2);
            d10 += __shfl_xor_sync(~0u, d10, 1); d10 += __shfl_xor_sync(~0u, d10, 2);
            d11 += __shfl_xor_sync(~0u, d11, 1); d11 += __shfl_xor_sync(~0u, d11, 2);
            if (m == 0) {
                dens[half * 128 + row0]      = d00;
                dens[half * 128 + row0 + 8]  = d01;
                dens[half * 128 + row0 + 16] = d10;
                dens[half * 128 + row0 + 24] = d11;
            }
        }
        if (st >= 1 && st != 4 && st != 9) {
            act_store(st <= 6 || st == 10); // relu except feature/out2 paths (st7 pre-relu'd)
            if (st != 10) zero_acc();
        }

        if (st >= 1) asm volatile("cp.async.wait_group 0;" ::: "memory");
        __syncthreads();                    // act + dens visible, weights resident

        if (st == 7 && half == 0 && m == 0) {   // combine density halves
#pragma unroll
            for (int rr = 0; rr < 4; rr++) {
                const int r = row0 + rr * 8;
                ostg[r * 4 + 3] = dens[r] + dens[128 + r];
            }
        }

        if (st == 0 || st == 3)      mma_src(sptr(posH), PSTR, 4);
        else if (st == 8)            mma_src(sptr(viewH), VSTR, 2);
        else if (st == 10) {                // rgb: K=128, N=8 (3 real), half 0 only
            if (half == 0) {
                float c8a[4] = {0.f, 0.f, 0.f, 0.f};
                float c8b[4] = {0.f, 0.f, 0.f, 0.f};
                const int arow = r0 + krow;
                for (int kt = 0; kt < 8; kt++) {
                    uint32_t ta0[4], ta1[4];
                    uint32_t ao = (uint32_t)(arow * ASTR + kt * 16 + nsel) * 2;
                    ldm4(ta0[0], ta0[1], ta0[2], ta0[3], ab + ao);
                    ldm4(ta1[0], ta1[1], ta1[2], ta1[3], ab + ao + (uint32_t)(16 * ASTR) * 2);
                    uint32_t b0, b1;
                    uint32_t wo = (uint32_t)((kt * 16 + krow) * WSTR) * 2;
                    ldm2t(b0, b1, wb + wo);
                    mma_f16(c8a, ta0, b0, b1);
                    mma_f16(c8b, ta1, b0, b1);
                }
                if (2 * m < 3) {
                    ostg[row0 * 4 + 2 * m]        = c8a[0];
                    ostg[(row0 + 8) * 4 + 2 * m]  = c8a[2];
                    ostg[(row0 + 16) * 4 + 2 * m] = c8b[0];
                    ostg[(row0 + 24) * 4 + 2 * m] = c8b[2];
                }
                if (2 * m + 1 < 3) {
                    ostg[row0 * 4 + 2 * m + 1]        = c8a[1];
                    ostg[(row0 + 8) * 4 + 2 * m + 1]  = c8a[3];
                    ostg[(row0 + 16) * 4 + 2 * m + 1] = c8b[1];
                    ostg[(row0 + 24) * 4 + 2 * m + 1] = c8b[3];
                }
            }
        } else                        mma_src(ab, ASTR, 8);
    }

    __syncthreads();
    if (tid < TILE)
        ((float4*)out)[tile * TILE + tid] = ((const float4*)ostg)[tid];
}

extern "C" void kernel_launch(void* const* d_in, const int* in_sizes, int n_in,
                              void* d_out, int out_size) {
    const float* x     = (const float*)d_in[0];
    const float* d1_W0 = (const float*)d_in[1];
    const float* d1_W1 = (const float*)d_in[2];
    const float* d1_W2 = (const float*)d_in[3];
    const float* d2_W0 = (const float*)d_in[4];
    const float* d2_W1 = (const float*)d_in[5];
    const float* d2_W2 = (const float*)d_in[6];
    const float* d2_W3 = (const float*)d_in[7];
    const float* c_W0  = (const float*)d_in[8];
    const float* c_W1  = (const float*)d_in[9];
    const int N = in_sizes[0] / 90;

    prep_kernel<<<1184, WSTR>>>(d1_W0, d1_W1, d1_W2, d2_W0, d2_W1, d2_W2, d2_W3, c_W0, c_W1);
    cudaFuncSetAttribute(nerf_main, cudaFuncAttributeMaxDynamicSharedMemorySize, SMEM_TOTAL);
    nerf_main<<<N / TILE, TPB, SMEM_TOTAL>>>(x, (float*)d_out);
}